// round 7
// baseline (speedup 1.0000x reference)
#include <cuda_runtime.h>

#define TT    1000
#define BB    16384
#define NTHR  32
#define NCH   6           // T-chunks (parallelized via warmup recomputation)
#define CHL   167         // base chunk length (last chunk: 999-5*167 = 164)
#define WARM  32          // warmup steps (RNN contraction -> exact to fp32)
#define WU    8           // warmup prefetch depth
#define UU    8           // rows per cp.async window
#define NWF   20          // full windows per chunk (167=20*8+7, 164=20*8+4)
#define NBLK  (NCH * 512)
#define DBY   (UU * 384)  // data bytes per smem buffer
#define EBY   (UU * 256)  // eps  bytes per smem buffer

__device__ double g_part[NBLK];
__device__ unsigned int g_cnt;   // zero-init; reset by the reducing block

__device__ __forceinline__ float ftanh(float x) {
    float r;
    asm("tanh.approx.f32 %0, %1;" : "=f"(r) : "f"(x));
    return r;
}
__device__ __forceinline__ float ldcs(const float* p) {
    float v;
    asm("ld.global.cs.f32 %0, [%1];" : "=f"(v) : "l"(p));
    return v;
}
__device__ __forceinline__ float2 ldcs2(const float* p) {
    float2 v;
    asm("ld.global.cs.v2.f32 {%0,%1}, [%2];" : "=f"(v.x), "=f"(v.y) : "l"(p));
    return v;
}
// Predicated 16B cp.async (L2-only path).
__device__ __forceinline__ void cpa16(unsigned s, const float* g, bool p) {
    asm volatile("{\n\t.reg .pred q;\n\tsetp.ne.b32 q, %2, 0;\n\t"
                 "@q cp.async.cg.shared.global [%0], [%1], 16;\n\t}"
                 :: "r"(s), "l"(g), "r"((int)p) : "memory");
}
#define CPCOMMIT() asm volatile("cp.async.commit_group;" ::: "memory")
#define CPWAIT1()  asm volatile("cp.async.wait_group 1;" ::: "memory")

__global__ void __launch_bounds__(NTHR, 21) elbo_main(
    const float* __restrict__ data, const float* __restrict__ eps,
    const float* __restrict__ W_ih, const float* __restrict__ W_hh,
    const float* __restrict__ b_ih, const float* __restrict__ b_hh,
    const float* __restrict__ h0,   const float* __restrict__ z0v,
    const float* __restrict__ Wt,   const float* __restrict__ bt,
    const float* __restrict__ We,   const float* __restrict__ be,
    float* __restrict__ out)
{
    __shared__ __align__(16) unsigned char sm[2 * (DBY + EBY)];

    const int blk   = blockIdx.x;
    const int chunk = blk >> 9;              // 0..5
    const int wb    = blk & 511;
    const int lane  = threadIdx.x;
    const int b     = wb * NTHR + lane;
    const int b0    = wb * NTHR;             // warp's first batch lane

    const int s = chunk * CHL;
    const int L = (chunk == NCH - 1) ? (TT - 1 - s) : CHL;   // 167 or 164

    const float* __restrict__ dwarp = data + (size_t)b0 * 3;
    const float* __restrict__ ewarp = eps  + (size_t)b0 * 2;
    const unsigned smB = (unsigned)__cvta_generic_to_shared(sm);

    // Fetch window W2 (rows s+1+UU*W2 ..) into buffer (W2&1).
    // Rows past TT-1 are skipped; rows past s+L but < TT are harmless overfetch.
#define ISSUE_WIN(W2)                                                      \
    do {                                                                   \
        const int _buf = (W2) & 1;                                         \
        const int _r0  = s + 1 + UU * (W2);                                \
        _Pragma("unroll")                                                  \
        for (int _u = 0; _u < UU; ++_u) {                                  \
            int _row = _r0 + _u;                                           \
            bool _v = (_row < TT);                                         \
            cpa16(smB + _buf * DBY + _u * 384 + lane * 16,                 \
                  dwarp + (size_t)_row * (3 * BB) + lane * 4,              \
                  _v && (lane < 24));                                      \
            cpa16(smB + 2 * DBY + _buf * EBY + _u * 256 + lane * 16,       \
                  ewarp + (size_t)_row * (2 * BB) + lane * 4,              \
                  _v && (lane < 16));                                      \
        }                                                                  \
    } while (0)

    ISSUE_WIN(0); CPCOMMIT();
    ISSUE_WIN(1); CPCOMMIT();

    // ---- Small params -> registers (broadcast loads). ----
    const float w00 = W_ih[0], w01 = W_ih[1], w02 = W_ih[2];
    const float w10 = W_ih[3], w11 = W_ih[4], w12 = W_ih[5];
    const float u00 = W_hh[0], u01 = W_hh[1], u10 = W_hh[2], u11 = W_hh[3];
    const float c0  = b_ih[0] + b_hh[0], c1 = b_ih[1] + b_hh[1];
    const float wt00 = Wt[0], wt01 = Wt[1], wt10 = Wt[2], wt11 = Wt[3];
    const float bt0 = bt[0], bt1 = bt[1];
    const float we00 = We[0], we01 = We[1];
    const float we10 = We[2], we11 = We[3];
    const float we20 = We[4], we21 = We[5];
    const float be0 = be[0], be1 = be[1], be2 = be[2];

    const size_t DS = 3ull * BB;
    const float* __restrict__ dbase = data + (size_t)b * 3;
    const float* __restrict__ ebase = eps  + (size_t)b * 2;

    float h0x, h1x, zp0, zp1;

    if (chunk == 0) {
        h0x = h0[0]; h1x = h0[1];
        zp0 = z0v[0]; zp1 = z0v[1];
    } else {
        // ---- Warmup: recompute h over rows [s-WARM, s-1] from h=0. ----
        const int a = s - WARM;
        float wd0[WU], wd1[WU], wd2[WU];
        const float* wp = dbase + (size_t)a * DS;
#pragma unroll
        for (int u = 0; u < WU; ++u) {
            const float* p = wp + (size_t)u * DS;
            wd0[u] = ldcs(p); wd1[u] = ldcs(p + 1); wd2[u] = ldcs(p + 2);
        }
        const float2 es = ldcs2(ebase + (size_t)s * (2ull * BB));
        h0x = 0.f; h1x = 0.f;

#define WSTEP(A0, A1, A2)                                                  \
        do {                                                               \
            float xw0 = c0 + w00*(A0) + w01*(A1) + w02*(A2);               \
            float xw1 = c1 + w10*(A0) + w11*(A1) + w12*(A2);               \
            float p0 = fmaf(u01, h1x, fmaf(u00, h0x, xw0));                \
            float p1 = fmaf(u11, h1x, fmaf(u10, h0x, xw1));                \
            h0x = ftanh(p0);                                               \
            h1x = ftanh(p1);                                               \
        } while (0)

        const float* pw = wp + (size_t)WU * DS;
#pragma unroll 1
        for (int w = 0; w < WARM / WU - 1; ++w) {
#pragma unroll
            for (int u = 0; u < WU; ++u) {
                float a0 = wd0[u], a1 = wd1[u], a2 = wd2[u];
                const float* p = pw + (size_t)u * DS;
                wd0[u] = ldcs(p); wd1[u] = ldcs(p + 1); wd2[u] = ldcs(p + 2);
                WSTEP(a0, a1, a2);
            }
            pw += (size_t)WU * DS;
        }
#pragma unroll
        for (int u = 0; u < WU; ++u)
            WSTEP(wd0[u], wd1[u], wd2[u]);
#undef WSTEP
        zp0 = fmaf(0.01f, es.x, h0x);
        zp1 = fmaf(0.01f, es.y, h1x);
    }

    // xc = c + W_ih·x (h-independent pre-activation part) for step s.
    float xc0, xc1;
    {
        const float* p = dbase + (size_t)s * DS;
        float a0 = ldcs(p), a1 = ldcs(p + 1), a2 = ldcs(p + 2);
        xc0 = c0 + w00*a0 + w01*a1 + w02*a2;
        xc1 = c1 + w10*a0 + w11*a1 + w12*a2;
    }

    float ra0 = 0.f, ra1 = 0.f, ra2 = 0.f, ra3 = 0.f, ra4 = 0.f;
    float ea0 = 0.f, ea1 = 0.f;

#define STEP(XN0, XN1, XN2, E0, E1)                                        \
    do {                                                                   \
        float pre0 = fmaf(u01, h1x, fmaf(u00, h0x, xc0));                  \
        float pre1 = fmaf(u11, h1x, fmaf(u10, h0x, xc1));                  \
        xc0 = c0 + w00*(XN0) + w01*(XN1) + w02*(XN2);                      \
        xc1 = c1 + w10*(XN0) + w11*(XN1) + w12*(XN2);                      \
        h0x = ftanh(pre0);                                                 \
        h1x = ftanh(pre1);                                                 \
        float zv0 = fmaf(0.01f, (E0), h0x);                                \
        float zv1 = fmaf(0.01f, (E1), h1x);                                \
        float zl0 = fmaf(wt01, zp1, fmaf(wt00, zp0, bt0));                 \
        float zl1 = fmaf(wt11, zp1, fmaf(wt10, zp0, bt1));                 \
        float r0 = zv0 - zl0, r1 = zv1 - zl1;                              \
        float xl0 = fmaf(we01, zv1, fmaf(we00, zv0, be0));                 \
        float xl1 = fmaf(we11, zv1, fmaf(we10, zv0, be1));                 \
        float xl2 = fmaf(we21, zv1, fmaf(we20, zv0, be2));                 \
        float q0 = (XN0) - xl0, q1 = (XN1) - xl1, q2 = (XN2) - xl2;        \
        ra0 = fmaf(r0, r0, ra0);                                           \
        ra1 = fmaf(r1, r1, ra1);                                           \
        ra2 = fmaf(q0, q0, ra2);                                           \
        ra3 = fmaf(q1, q1, ra3);                                           \
        ra4 = fmaf(q2, q2, ra4);                                           \
        ea0 = fmaf((E0), (E0), ea0);                                       \
        ea1 = fmaf((E1), (E1), ea1);                                       \
        zp0 = zv0; zp1 = zv1;                                              \
    } while (0)

    // Read smem row _u of buffer BUF into 5 regs (conflict-free LDS).
#define LOAD_ROW(BUF, U, X0, X1, X2, E0, E1)                               \
    do {                                                                   \
        const float* _dp = (const float*)(sm + (BUF)*DBY + (U)*384         \
                                          + lane*12);                      \
        X0 = _dp[0]; X1 = _dp[1]; X2 = _dp[2];                             \
        const float2 _ep = *(const float2*)(sm + 2*DBY + (BUF)*EBY         \
                                            + (U)*256 + lane*8);           \
        E0 = _ep.x; E1 = _ep.y;                                            \
    } while (0)

    // ---- NWF full windows, row-by-row consumption with 1-row lookahead ----
#pragma unroll 1
    for (int w = 0; w < NWF; ++w) {
        CPWAIT1();
        __syncwarp();
        const int buf = w & 1;
        float nx0, nx1, nx2, ne0, ne1;
        LOAD_ROW(buf, 0, nx0, nx1, nx2, ne0, ne1);
#pragma unroll
        for (int u = 0; u < UU; ++u) {
            float x0c = nx0, x1c = nx1, x2c = nx2, e0c = ne0, e1c = ne1;
            if (u < UU - 1)
                LOAD_ROW(buf, u + 1, nx0, nx1, nx2, ne0, ne1);
            STEP(x0c, x1c, x2c, e0c, e1c);
        }
        if (w + 2 <= NWF) ISSUE_WIN(w + 2);   // fetch next window for this buf
        CPCOMMIT();
    }

    // ---- Tail window (rem = L - NWF*UU steps: 7 or 4) ----
    {
        CPWAIT1();
        __syncwarp();
        const int rem = L - NWF * UU;
        const int buf = NWF & 1;
#pragma unroll
        for (int u = 0; u < UU - 1; ++u) {
            if (u < rem) {
                float x0c, x1c, x2c, e0c, e1c;
                LOAD_ROW(buf, u, x0c, x1c, x2c, e0c, e1c);
                STEP(x0c, x1c, x2c, e0c, e1c);
            }
        }
    }
#undef STEP
#undef LOAD_ROW
#undef ISSUE_WIN

    // Per-thread contribution -> double, warp reduce.
    double part = -5000.0 * ((double)ra0 + (double)ra1 + (double)ra2 +
                             (double)ra3 + (double)ra4)
                + 0.5 * ((double)ea0 + (double)ea1);
#pragma unroll
    for (int o = 16; o > 0; o >>= 1)
        part += __shfl_down_sync(0xffffffffu, part, o);

    // Last-arriving block performs the final deterministic reduction.
    unsigned int old = 0;
    if (lane == 0) {
        g_part[blk] = part;
        __threadfence();
        old = atomicAdd(&g_cnt, 1u);
    }
    old = __shfl_sync(0xffffffffu, old, 0);
    if (old == NBLK - 1) {
        __threadfence();
        double acc = 0.0;
#pragma unroll
        for (int k = 0; k < NBLK / 32; ++k)
            acc += __ldcg(&g_part[lane + k * 32]);
#pragma unroll
        for (int o = 16; o > 0; o >>= 1)
            acc += __shfl_down_sync(0xffffffffu, acc, o);
        if (lane == 0) {
            g_cnt = 0;   // reset for the next (graph-replayed) launch
            // Telescoped normal-logprob constants:
            // -(T-1)*B*X_DIM * (ln(sigma) + 0.5*ln(2*pi))
            const double CST = -(double)(TT - 1) * (double)BB * 3.0 *
                               (-4.605170185988091 + 0.9189385332046727);
            out[0] = (float)(acc + CST);
        }
    }
}

extern "C" void kernel_launch(void* const* d_in, const int* in_sizes, int n_in,
                              void* d_out, int out_size)
{
    const float* data = (const float*)d_in[0];
    const float* eps  = (const float*)d_in[1];
    const float* W_ih = (const float*)d_in[2];
    const float* W_hh = (const float*)d_in[3];
    const float* b_ih = (const float*)d_in[4];
    const float* b_hh = (const float*)d_in[5];
    const float* h0   = (const float*)d_in[6];
    const float* z0   = (const float*)d_in[7];
    const float* Wt   = (const float*)d_in[8];
    const float* bt   = (const float*)d_in[9];
    const float* We   = (const float*)d_in[10];
    const float* be   = (const float*)d_in[11];

    // Maximize smem carveout so 21 blocks/SM fit (215KB static smem demand).
    cudaFuncSetAttribute(elbo_main,
                         cudaFuncAttributePreferredSharedMemoryCarveout, 100);

    elbo_main<<<NBLK, NTHR>>>(data, eps, W_ih, W_hh, b_ih, b_hh,
                              h0, z0, Wt, bt, We, be, (float*)d_out);
}